// round 15
// baseline (speedup 1.0000x reference)
#include <cuda_runtime.h>
#include <cstdint>

#define MAX_N 100000
#define IN_DIM 192
#define NEG_SLOPE 0.2f
#define EDGE_ILP 4

// Scratch (allocation-free rule: __device__ globals).
__device__ float4 g_rec[MAX_N];    // {xproj0, xproj1, a_src, a_dst}
__device__ float  g_adst[MAX_N];   // dense a_dst copy (L1-friendlier gathers)
__device__ float4 g_acc[MAX_N];    // {sum e*xp0, sum e*xp1, sum e, pad}
__device__ int    g_is64;          // 1 if edge_index is int64, 0 if int32

// ---------------------------------------------------------------------------
// Kernel 1: projection + logits + self-loop init. NON-persistent (one
// 2-node warp-iteration per warp, R9 body) so blocks retire continuously
// and the PDL-dependent edge kernel can start prefetching in K1's shadow.
// Block 0 warp 0 additionally runs the int64/int32 detector.
// ---------------------------------------------------------------------------
__global__ __launch_bounds__(256)
void gat_project_kernel(const float* __restrict__ x,
                        const float* __restrict__ W,        // [IN_DIM,2]
                        const float* __restrict__ att_src,  // [2]
                        const float* __restrict__ att_dst,  // [2]
                        const int* __restrict__ eidx_w,     // edge_index words
                        int det_nwords,                     // 0 => force is64=1
                        int N)
{
    cudaTriggerProgrammaticLaunchCompletion();   // allow K2 to launch early

    if (blockIdx.x == 0 && threadIdx.x < 32) {
        int notz = 0;
        if (det_nwords > 0) {
            for (int i = threadIdx.x; i < 2048; i += 32) {
                int p = 2 * i + 1;                 // odd 32-bit words
                if (p < det_nwords && eidx_w[p] != 0) notz = 1;
            }
        }
        notz = __any_sync(0xffffffffu, notz);
        if (threadIdx.x == 0) g_is64 = (det_nwords > 0) ? (notz ? 0 : 1) : 1;
    }

    int lane = threadIdx.x & 31;
    int warp = (blockIdx.x * blockDim.x + threadIdx.x) >> 5;
    int n0   = 2 * warp;
    if (n0 >= N) return;

    const float4* W4 = (const float4*)W;
    float4 w0 = __ldg(W4 + lane);
    float4 w1 = __ldg(W4 + lane + 32);
    float4 w2 = __ldg(W4 + lane + 64);
    float as0 = __ldg(att_src + 0), as1 = __ldg(att_src + 1);
    float ad0 = __ldg(att_dst + 0), ad1 = __ldg(att_dst + 1);

    int nA = n0;
    int nB = (n0 + 1 < N) ? (n0 + 1) : n0;         // clamp (safe duplicate load)

    const float2* xrA = (const float2*)(x + (size_t)nA * IN_DIM);
    const float2* xrB = (const float2*)(x + (size_t)nB * IN_DIM);
    float2 a0 = __ldg(xrA + lane);
    float2 b0 = __ldg(xrB + lane);
    float2 a1 = __ldg(xrA + lane + 32);
    float2 b1 = __ldg(xrB + lane + 32);
    float2 a2 = __ldg(xrA + lane + 64);
    float2 b2 = __ldg(xrB + lane + 64);

    float pA0 = a0.x * w0.x + a0.y * w0.z
              + a1.x * w1.x + a1.y * w1.z
              + a2.x * w2.x + a2.y * w2.z;
    float pA1 = a0.x * w0.y + a0.y * w0.w
              + a1.x * w1.y + a1.y * w1.w
              + a2.x * w2.y + a2.y * w2.w;
    float pB0 = b0.x * w0.x + b0.y * w0.z
              + b1.x * w1.x + b1.y * w1.z
              + b2.x * w2.x + b2.y * w2.z;
    float pB1 = b0.x * w0.y + b0.y * w0.w
              + b1.x * w1.y + b1.y * w1.w
              + b2.x * w2.y + b2.y * w2.w;

#pragma unroll
    for (int off = 16; off > 0; off >>= 1) {       // 4 independent chains
        pA0 += __shfl_xor_sync(0xffffffffu, pA0, off);
        pA1 += __shfl_xor_sync(0xffffffffu, pA1, off);
        pB0 += __shfl_xor_sync(0xffffffffu, pB0, off);
        pB1 += __shfl_xor_sync(0xffffffffu, pB1, off);
    }

    if (lane == 0) {
        {
            float a_s = pA0 * as0 + pA1 * as1;
            float a_d = pA0 * ad0 + pA1 * ad1;
            g_rec[nA]  = make_float4(pA0, pA1, a_s, a_d);
            g_adst[nA] = a_d;
            float alpha = a_s + a_d;               // self-loop edge
            alpha = (alpha >= 0.f) ? alpha : NEG_SLOPE * alpha;
            float ev = __expf(alpha);
            g_acc[nA] = make_float4(ev * pA0, ev * pA1, ev, 0.f);
        }
        if (n0 + 1 < N) {
            float a_s = pB0 * as0 + pB1 * as1;
            float a_d = pB0 * ad0 + pB1 * ad1;
            g_rec[nB]  = make_float4(pB0, pB1, a_s, a_d);
            g_adst[nB] = a_d;
            float alpha = a_s + a_d;
            alpha = (alpha >= 0.f) ? alpha : NEG_SLOPE * alpha;
            float ev = __expf(alpha);
            g_acc[nB] = make_float4(ev * pB0, ev * pB1, ev, 0.f);
        }
    }
}

// ---------------------------------------------------------------------------
// Kernel 2 (PDL): prefetch edge indices into registers BEFORE the grid
// dependency sync (overlapping K1), then gather + fused softmax + v4 REDG.
// host_is64: 1 => buffer certainly int64 (prefetch 64-bit view);
//            0 => ambiguous: prefetch int32 view (bounds-safe either way),
//                 reload as int64 after sync if detector says so.
// ---------------------------------------------------------------------------
__global__ __launch_bounds__(256)
void gat_edge_kernel(const void* __restrict__ edge_index, int E, int N,
                     int host_is64)
{
    cudaTriggerProgrammaticLaunchCompletion();

    int base = blockIdx.x * (256 * EDGE_ILP) + threadIdx.x;

    int s[EDGE_ILP], d[EDGE_ILP];
#pragma unroll
    for (int i = 0; i < EDGE_ILP; i++) { s[i] = -1; d[i] = -1; }

    if (host_is64) {
        const long long* ei = (const long long*)edge_index;
#pragma unroll
        for (int i = 0; i < EDGE_ILP; i++) {
            int e = base + i * 256;
            if (e < E) {
                s[i] = (int)__ldg(ei + e);
                d[i] = (int)__ldg(ei + E + e);
            }
        }
    } else {
        const int* ei = (const int*)edge_index;
#pragma unroll
        for (int i = 0; i < EDGE_ILP; i++) {
            int e = base + i * 256;
            if (e < E) {                       // int32 view: safe in both cases
                s[i] = __ldg(ei + e);
                d[i] = __ldg(ei + E + e);
            }
        }
    }

    cudaGridDependencySynchronize();           // wait for K1 completion

    if (!host_is64 && g_is64) {                // ambiguous turned out int64
        const long long* ei = (const long long*)edge_index;
#pragma unroll
        for (int i = 0; i < EDGE_ILP; i++) {
            int e = base + i * 256;
            if (e < E) {
                s[i] = (int)__ldg(ei + e);
                d[i] = (int)__ldg(ei + E + e);
            }
        }
    }

    float4 rs[EDGE_ILP];
    float  ad[EDGE_ILP];
#pragma unroll
    for (int i = 0; i < EDGE_ILP; i++) {
        if ((unsigned)s[i] < (unsigned)N && (unsigned)d[i] < (unsigned)N) {
            rs[i] = __ldg(&g_rec[s[i]]);       // 16B gather
            ad[i] = __ldg(&g_adst[d[i]]);      // 4B gather, dense array
        }
    }

#pragma unroll
    for (int i = 0; i < EDGE_ILP; i++) {
        if ((unsigned)s[i] < (unsigned)N && (unsigned)d[i] < (unsigned)N) {
            float alpha = rs[i].z + ad[i];
            alpha = (alpha >= 0.f) ? alpha : NEG_SLOPE * alpha;
            float ev = __expf(alpha);
            float v0 = ev * rs[i].x;
            float v1 = ev * rs[i].y;
            asm volatile("red.global.add.v4.f32 [%0], {%1, %2, %3, %4};"
                         :: "l"(&g_acc[d[i]]), "f"(v0), "f"(v1), "f"(ev), "f"(0.f)
                         : "memory");
        }
    }
}

// ---------------------------------------------------------------------------
// Kernel 3 (PDL): normalize + bias. Launches early, syncs, then reads g_acc.
// ---------------------------------------------------------------------------
__global__ __launch_bounds__(256)
void gat_final_kernel(float* __restrict__ out,
                      const float* __restrict__ bias,
                      int N)
{
    int i = blockIdx.x * blockDim.x + threadIdx.x;   // pair index
    int n0 = 2 * i;
    float b0 = __ldg(bias + 0), b1 = __ldg(bias + 1);

    cudaGridDependencySynchronize();           // wait for K2 completion

    if (n0 >= N) return;
    float4 a0 = g_acc[n0];
    float inv0 = 1.0f / (a0.z + 1e-16f);
    if (n0 + 1 < N) {
        float4 a1 = g_acc[n0 + 1];
        float inv1 = 1.0f / (a1.z + 1e-16f);
        float4 o = make_float4(a0.x * inv0 + b0, a0.y * inv0 + b1,
                               a1.x * inv1 + b0, a1.y * inv1 + b1);
        ((float4*)out)[i] = o;
    } else {
        ((float2*)out)[n0] = make_float2(a0.x * inv0 + b0, a0.y * inv0 + b1);
    }
}

// ---------------------------------------------------------------------------
// Input identification by element count (robust to metadata ordering):
//   x = largest; edge_index = 2nd; edge_attr = 3rd (gives E); W = 384;
//   att_src, att_dst, bias = the three size-2 tensors in appearance order.
// ---------------------------------------------------------------------------
extern "C" void kernel_launch(void* const* d_in, const int* in_sizes, int n_in,
                              void* d_out, int out_size)
{
    int i_x = -1, i_eidx = -1, i_attr = -1, i_W = -1;
    int small[3] = {-1, -1, -1};
    int nsmall = 0;
    {
        long long best = -1;
        for (int i = 0; i < n_in; i++)
            if (in_sizes[i] > best) { best = in_sizes[i]; i_x = i; }
        best = -1;
        for (int i = 0; i < n_in; i++)
            if (i != i_x && in_sizes[i] > best) { best = in_sizes[i]; i_eidx = i; }
        best = -1;
        for (int i = 0; i < n_in; i++)
            if (i != i_x && i != i_eidx && in_sizes[i] > best) { best = in_sizes[i]; i_attr = i; }
    }
    for (int i = 0; i < n_in; i++) {
        if (i == i_x || i == i_eidx || i == i_attr) continue;
        if (in_sizes[i] > 16) { i_W = i; }
        else if (nsmall < 3) { small[nsmall++] = i; }
    }

    const float* x       = (const float*)d_in[i_x];
    const void*  eidx    = d_in[i_eidx];
    const float* W       = (const float*)d_in[i_W];
    const float* att_src = (const float*)d_in[small[0]];
    const float* att_dst = (const float*)d_in[small[1]];
    const float* bias    = (const float*)d_in[small[2]];
    float* out           = (float*)d_out;

    int N = in_sizes[i_x] / IN_DIM;
    int E = in_sizes[i_attr];               // edge_attr is [E,1]
    int eidx_elems = in_sizes[i_eidx];

    // ratio 4E => certainly int64 (word count); ratio 2E => ambiguous.
    int host_is64  = (eidx_elems == 4 * E) ? 1 : 0;
    int det_nwords = host_is64 ? 0 : (2 * E);

    // K1: non-persistent, 16 nodes/block
    int grid1 = (N + 15) / 16;
    gat_project_kernel<<<grid1, 256>>>(x, W, att_src, att_dst,
                                       (const int*)eidx, det_nwords, N);

    // K2 with PDL: prefetch indices in K1's shadow
    {
        cudaLaunchConfig_t cfg = {};
        cfg.gridDim  = dim3((E + 256 * EDGE_ILP - 1) / (256 * EDGE_ILP), 1, 1);
        cfg.blockDim = dim3(256, 1, 1);
        cfg.stream   = 0;
        cudaLaunchAttribute attr[1];
        attr[0].id = cudaLaunchAttributeProgrammaticStreamSerialization;
        attr[0].val.programmaticStreamSerializationAllowed = 1;
        cfg.attrs = attr;
        cfg.numAttrs = 1;
        cudaLaunchKernelEx(&cfg, gat_edge_kernel, eidx, E, N, host_is64);
    }

    // K3 with PDL: removes the trailing launch gap
    {
        int pairs = (N + 1) / 2;
        cudaLaunchConfig_t cfg = {};
        cfg.gridDim  = dim3((pairs + 255) / 256, 1, 1);
        cfg.blockDim = dim3(256, 1, 1);
        cfg.stream   = 0;
        cudaLaunchAttribute attr[1];
        attr[0].id = cudaLaunchAttributeProgrammaticStreamSerialization;
        attr[0].val.programmaticStreamSerializationAllowed = 1;
        cfg.attrs = attr;
        cfg.numAttrs = 1;
        cudaLaunchKernelEx(&cfg, gat_final_kernel, out, bias, N);
    }
}

// round 16
// speedup vs baseline: 1.0203x; 1.0203x over previous
#include <cuda_runtime.h>
#include <cstdint>

#define MAX_N 100000
#define IN_DIM 192
#define NEG_SLOPE 0.2f
#define EDGE_ILP 4

// Scratch (allocation-free rule: __device__ globals).
// g_xp[n]   = {xproj0, xproj1}  (8B gather target; a_src recomputed in K2)
// g_adst[n] = a_dst             (4B gather target)
// g_acc[n]  = {sum e*xp0, sum e*xp1, sum e, pad}
__device__ float2 g_xp[MAX_N];
__device__ float  g_adst[MAX_N];
__device__ float4 g_acc[MAX_N];
__device__ int    g_is64;   // 1 if edge_index is int64, 0 if int32

// ---------------------------------------------------------------------------
// Kernel 1 (R9 best body): projection + logits + self-loop init.
// Warp-per-node, TWO nodes per warp-iteration (4 independent reduce chains).
// Block 0 warp 0 additionally runs the int64/int32 detector.
// ---------------------------------------------------------------------------
__global__ __launch_bounds__(256)
void gat_project_kernel(const float* __restrict__ x,
                        const float* __restrict__ W,        // [IN_DIM,2]
                        const float* __restrict__ att_src,  // [2]
                        const float* __restrict__ att_dst,  // [2]
                        const int* __restrict__ eidx_w,     // edge_index words
                        int det_nwords,                     // 0 => force is64=1
                        int N)
{
    if (blockIdx.x == 0 && threadIdx.x < 32) {
        int notz = 0;
        if (det_nwords > 0) {
            for (int i = threadIdx.x; i < 2048; i += 32) {
                int p = 2 * i + 1;                 // odd 32-bit words
                if (p < det_nwords && eidx_w[p] != 0) notz = 1;
            }
        }
        notz = __any_sync(0xffffffffu, notz);
        if (threadIdx.x == 0) g_is64 = (det_nwords > 0) ? (notz ? 0 : 1) : 1;
    }

    int lane  = threadIdx.x & 31;
    int warp  = (blockIdx.x * blockDim.x + threadIdx.x) >> 5;
    int nwarp = (gridDim.x * blockDim.x) >> 5;

    const float4* W4 = (const float4*)W;
    float4 w0 = __ldg(W4 + lane);
    float4 w1 = __ldg(W4 + lane + 32);
    float4 w2 = __ldg(W4 + lane + 64);
    float as0 = __ldg(att_src + 0), as1 = __ldg(att_src + 1);
    float ad0 = __ldg(att_dst + 0), ad1 = __ldg(att_dst + 1);

    for (int n0 = 2 * warp; n0 < N; n0 += 2 * nwarp) {
        int nA = n0;
        int nB = (n0 + 1 < N) ? (n0 + 1) : n0;     // clamp (safe duplicate load)

        const float2* xrA = (const float2*)(x + (size_t)nA * IN_DIM);
        const float2* xrB = (const float2*)(x + (size_t)nB * IN_DIM);
        float2 a0 = __ldg(xrA + lane);
        float2 b0 = __ldg(xrB + lane);
        float2 a1 = __ldg(xrA + lane + 32);
        float2 b1 = __ldg(xrB + lane + 32);
        float2 a2 = __ldg(xrA + lane + 64);
        float2 b2 = __ldg(xrB + lane + 64);

        float pA0 = a0.x * w0.x + a0.y * w0.z
                  + a1.x * w1.x + a1.y * w1.z
                  + a2.x * w2.x + a2.y * w2.z;
        float pA1 = a0.x * w0.y + a0.y * w0.w
                  + a1.x * w1.y + a1.y * w1.w
                  + a2.x * w2.y + a2.y * w2.w;
        float pB0 = b0.x * w0.x + b0.y * w0.z
                  + b1.x * w1.x + b1.y * w1.z
                  + b2.x * w2.x + b2.y * w2.z;
        float pB1 = b0.x * w0.y + b0.y * w0.w
                  + b1.x * w1.y + b1.y * w1.w
                  + b2.x * w2.y + b2.y * w2.w;

#pragma unroll
        for (int off = 16; off > 0; off >>= 1) {   // 4 independent chains
            pA0 += __shfl_xor_sync(0xffffffffu, pA0, off);
            pA1 += __shfl_xor_sync(0xffffffffu, pA1, off);
            pB0 += __shfl_xor_sync(0xffffffffu, pB0, off);
            pB1 += __shfl_xor_sync(0xffffffffu, pB1, off);
        }

        if (lane == 0) {
            {
                float a_s = pA0 * as0 + pA1 * as1;
                float a_d = pA0 * ad0 + pA1 * ad1;
                g_xp[nA]   = make_float2(pA0, pA1);
                g_adst[nA] = a_d;
                float alpha = a_s + a_d;           // self-loop edge
                alpha = (alpha >= 0.f) ? alpha : NEG_SLOPE * alpha;
                float ev = __expf(alpha);
                g_acc[nA] = make_float4(ev * pA0, ev * pA1, ev, 0.f);
            }
            if (n0 + 1 < N) {
                float a_s = pB0 * as0 + pB1 * as1;
                float a_d = pB0 * ad0 + pB1 * ad1;
                g_xp[nB]   = make_float2(pB0, pB1);
                g_adst[nB] = a_d;
                float alpha = a_s + a_d;
                alpha = (alpha >= 0.f) ? alpha : NEG_SLOPE * alpha;
                float ev = __expf(alpha);
                g_acc[nB] = make_float4(ev * pB0, ev * pB1, ev, 0.f);
            }
        }
    }
}

// ---------------------------------------------------------------------------
// Kernel 2: single fused pass over edges, ILP=4. Gather working set shrunk
// to 1.2 MB (g_xp 8B + g_adst 4B); a_src recomputed from xp with 2 FMA —
// higher L1 hit rate on gathers -> fewer LTS sectors.
//   alpha = leakyrelu(a_src[s] + a_dst[d]); e = exp(alpha)
//   acc[d] += {e*xp0[s], e*xp1[s], e, 0}  via one red.global.add.v4.f32
// (softmax max-subtraction elided: scale-invariant; fp32-safe here)
// ---------------------------------------------------------------------------
__global__ __launch_bounds__(256)
void gat_edge_kernel(const void* __restrict__ edge_index, int E, int N,
                     const float* __restrict__ att_src)
{
    int base = blockIdx.x * (256 * EDGE_ILP) + threadIdx.x;
    int is64 = g_is64;
    bool full = (blockIdx.x + 1) * (256 * EDGE_ILP) <= E;
    float as0 = __ldg(att_src + 0), as1 = __ldg(att_src + 1);

    int s[EDGE_ILP], d[EDGE_ILP];
    if (full) {
#pragma unroll
        for (int i = 0; i < EDGE_ILP; i++) {
            int e = base + i * 256;
            if (is64) {
                const long long* ei = (const long long*)edge_index;
                s[i] = (int)__ldg(ei + e);
                d[i] = (int)__ldg(ei + E + e);
            } else {
                const int* ei = (const int*)edge_index;
                s[i] = __ldg(ei + e);
                d[i] = __ldg(ei + E + e);
            }
        }
    } else {
#pragma unroll
        for (int i = 0; i < EDGE_ILP; i++) {
            int e = base + i * 256;
            s[i] = -1; d[i] = -1;
            if (e < E) {
                if (is64) {
                    const long long* ei = (const long long*)edge_index;
                    s[i] = (int)__ldg(ei + e);
                    d[i] = (int)__ldg(ei + E + e);
                } else {
                    const int* ei = (const int*)edge_index;
                    s[i] = __ldg(ei + e);
                    d[i] = __ldg(ei + E + e);
                }
            }
        }
    }

    float2 xp[EDGE_ILP];
    float  ad[EDGE_ILP];
#pragma unroll
    for (int i = 0; i < EDGE_ILP; i++) {
        if ((unsigned)s[i] < (unsigned)N && (unsigned)d[i] < (unsigned)N) {
            xp[i] = __ldg(&g_xp[s[i]]);         // 8B gather (was 16B)
            ad[i] = __ldg(&g_adst[d[i]]);       // 4B gather
        }
    }

#pragma unroll
    for (int i = 0; i < EDGE_ILP; i++) {
        if ((unsigned)s[i] < (unsigned)N && (unsigned)d[i] < (unsigned)N) {
            float a_s = xp[i].x * as0 + xp[i].y * as1;   // recompute a_src
            float alpha = a_s + ad[i];
            alpha = (alpha >= 0.f) ? alpha : NEG_SLOPE * alpha;
            float ev = __expf(alpha);
            float v0 = ev * xp[i].x;
            float v1 = ev * xp[i].y;
            asm volatile("red.global.add.v4.f32 [%0], {%1, %2, %3, %4};"
                         :: "l"(&g_acc[d[i]]), "f"(v0), "f"(v1), "f"(ev), "f"(0.f)
                         : "memory");
        }
    }
}

// ---------------------------------------------------------------------------
// Kernel 3: normalize + bias. 2 nodes/thread, packed float4 store.
// ---------------------------------------------------------------------------
__global__ __launch_bounds__(256)
void gat_final_kernel(float* __restrict__ out,
                      const float* __restrict__ bias,
                      int N)
{
    int i = blockIdx.x * blockDim.x + threadIdx.x;   // pair index
    int n0 = 2 * i;
    if (n0 >= N) return;
    float b0 = __ldg(bias + 0), b1 = __ldg(bias + 1);

    float4 a0 = g_acc[n0];
    float inv0 = 1.0f / (a0.z + 1e-16f);
    if (n0 + 1 < N) {
        float4 a1 = g_acc[n0 + 1];
        float inv1 = 1.0f / (a1.z + 1e-16f);
        float4 o = make_float4(a0.x * inv0 + b0, a0.y * inv0 + b1,
                               a1.x * inv1 + b0, a1.y * inv1 + b1);
        ((float4*)out)[i] = o;
    } else {
        ((float2*)out)[n0] = make_float2(a0.x * inv0 + b0, a0.y * inv0 + b1);
    }
}

// ---------------------------------------------------------------------------
// Input identification by element count (robust to metadata ordering):
//   x = largest; edge_index = 2nd; edge_attr = 3rd (gives E); W = 384;
//   att_src, att_dst, bias = the three size-2 tensors in appearance order.
// ---------------------------------------------------------------------------
extern "C" void kernel_launch(void* const* d_in, const int* in_sizes, int n_in,
                              void* d_out, int out_size)
{
    int i_x = -1, i_eidx = -1, i_attr = -1, i_W = -1;
    int small[3] = {-1, -1, -1};
    int nsmall = 0;
    {
        long long best = -1;
        for (int i = 0; i < n_in; i++)
            if (in_sizes[i] > best) { best = in_sizes[i]; i_x = i; }
        best = -1;
        for (int i = 0; i < n_in; i++)
            if (i != i_x && in_sizes[i] > best) { best = in_sizes[i]; i_eidx = i; }
        best = -1;
        for (int i = 0; i < n_in; i++)
            if (i != i_x && i != i_eidx && in_sizes[i] > best) { best = in_sizes[i]; i_attr = i; }
    }
    for (int i = 0; i < n_in; i++) {
        if (i == i_x || i == i_eidx || i == i_attr) continue;
        if (in_sizes[i] > 16) { i_W = i; }
        else if (nsmall < 3) { small[nsmall++] = i; }
    }

    const float* x       = (const float*)d_in[i_x];
    const void*  eidx    = d_in[i_eidx];
    const float* W       = (const float*)d_in[i_W];
    const float* att_src = (const float*)d_in[small[0]];
    const float* att_dst = (const float*)d_in[small[1]];
    const float* bias    = (const float*)d_in[small[2]];
    float* out           = (float*)d_out;

    int N = in_sizes[i_x] / IN_DIM;
    int E = in_sizes[i_attr];               // edge_attr is [E,1]
    int eidx_elems = in_sizes[i_eidx];

    // dtype: ratio 4 => int64 reported as word count (det_nwords=0 => force 64).
    // ratio 2 => ambiguous; K1 block 0 samples odd words on device.
    int det_nwords = (eidx_elems == 4 * E) ? 0 : (2 * E);

    // K1: persistent warp loop, 2 nodes per warp-iteration (R9 best: 1184)
    gat_project_kernel<<<1184, 256>>>(x, W, att_src, att_dst,
                                      (const int*)eidx, det_nwords, N);

    // K2: ILP=4 edges per thread, full grid
    int blocks2 = (E + 256 * EDGE_ILP - 1) / (256 * EDGE_ILP);
    gat_edge_kernel<<<blocks2, 256>>>(eidx, E, N, att_src);

    // K3: normalize + bias, 2 nodes/thread
    int pairs = (N + 1) / 2;
    gat_final_kernel<<<(pairs + 255) / 256, 256>>>(out, bias, N);
}